// round 14
// baseline (speedup 1.0000x reference)
#include <cuda_runtime.h>
#include <math.h>

// ---------------- static config ----------------
#define BB    8
#define SS    256      // tokens = 16x16 grid
#define CC    128
#define HWD   256      // H*W = 16*16
#define HEADS 4
#define DH    32
#define NWIN  16       // 4x4 windows
#define TT    16       // tokens per window
#define TOK_STRIDE 32768   // CC*HWD
#define TOTAL (BB*SS*CC*HWD)   // 67,108,864 floats (256 MB)

// ---------------- scratch (device globals; no allocation allowed) ----------------
__device__ float g_vn[TOTAL];   // normalized input / normalized mid
__device__ float g_q[TOTAL];    // Q, later reused as attention output (o_buf)
__device__ float g_k[TOTAL];    // K, later reused as MLP hidden
__device__ float g_v[TOTAL];    // V
__device__ float g_attn[BB*NWIN*HEADS*TT*TT];  // softmaxed probs

// ---------------- helpers ----------------
__device__ __forceinline__ float gelu_tanh(float x) {
    float x3 = x * x * x;
    return 0.5f * x * (1.0f + tanhf(0.7978845608028654f * (x + 0.044715f * x3)));
}

// rolled-frame position (pr,pc) -> original token index (roll by -SHIFT means
// content at rolled index p came from original index p+2 mod 16)
__device__ __forceinline__ int tok_of(int n, int slot) {
    int nr = n >> 2, nc = n & 3;
    int tr = slot >> 2, tc = slot & 3;
    int pr = nr * 4 + tr, pc = nc * 4 + tc;
    return (((pr + 2) & 15) << 4) | ((pc + 2) & 15);
}

__device__ __forceinline__ int region_of(int p) { return p < 12 ? 0 : (p < 14 ? 1 : 2); }

// ---------------- K1/K6: InstanceNorm over spatial dims ----------------
// one warp per (b,s,c) row of 256 floats; 8 rows per block
__global__ __launch_bounds__(256) void inorm_kernel(const float* __restrict__ in,
                                                    float* __restrict__ out) {
    int row  = blockIdx.x * 8 + (threadIdx.x >> 5);
    int lane = threadIdx.x & 31;
    const float* p = in + row * 256 + lane * 8;
    float4 a = *(const float4*)p;
    float4 b = *(const float4*)(p + 4);
    float s = a.x + a.y + a.z + a.w + b.x + b.y + b.z + b.w;
    float q = a.x*a.x + a.y*a.y + a.z*a.z + a.w*a.w
            + b.x*b.x + b.y*b.y + b.z*b.z + b.w*b.w;
#pragma unroll
    for (int off = 16; off; off >>= 1) {
        s += __shfl_xor_sync(0xffffffffu, s, off);
        q += __shfl_xor_sync(0xffffffffu, q, off);
    }
    float mean = s * (1.0f / 256.0f);
    float var  = q * (1.0f / 256.0f) - mean * mean;
    float inv  = rsqrtf(var + 1e-5f);
    float* o = out + row * 256 + lane * 8;
    float4 oa, ob;
    oa.x = (a.x - mean) * inv; oa.y = (a.y - mean) * inv;
    oa.z = (a.z - mean) * inv; oa.w = (a.w - mean) * inv;
    ob.x = (b.x - mean) * inv; ob.y = (b.y - mean) * inv;
    ob.z = (b.z - mean) * inv; ob.w = (b.w - mean) * inv;
    *(float4*)o = oa;
    *(float4*)(o + 4) = ob;
}

// ---------------- K2/K5/K7/K8: pointwise-conv GEMM ----------------
// per (b,s): Out[d][hw] = sum_c X[c][hw] * W[c][d] + bias[d]   (X,Out: [128][256])
// Block = one (bs, mat, hw-half): tile 128(d) x 128(hw), 256 thr, 8x8/thread.
// mode: 0 = store, 1 = gelu+store, 2 = res+val store
__global__ __launch_bounds__(256, 2) void pw_kernel(
    const float* __restrict__ X,
    const float* __restrict__ W0, const float* __restrict__ W1, const float* __restrict__ W2,
    const float* __restrict__ B0, const float* __restrict__ B1, const float* __restrict__ B2,
    float* __restrict__ O0, float* __restrict__ O1, float* __restrict__ O2,
    const float* __restrict__ res, int mode)
{
    __shared__ float Xs[16][128];
    __shared__ float Ws[16][128];
    const int bs  = blockIdx.y;
    const int mat = blockIdx.x >> 1;
    const int hw0 = (blockIdx.x & 1) * 128;
    const float* W  = (mat == 0) ? W0 : (mat == 1 ? W1 : W2);
    const float* Bp = (mat == 0) ? B0 : (mat == 1 ? B1 : B2);
    float*       O  = (mat == 0) ? O0 : (mat == 1 ? O1 : O2);
    const float* Xb = X + bs * TOK_STRIDE + hw0;
    float*       Ob = O + bs * TOK_STRIDE + hw0;
    const int tid = threadIdx.x;
    const int ty = tid >> 4, tx = tid & 15;

    float acc[2][2][4][4];
#pragma unroll
    for (int ii = 0; ii < 2; ii++)
#pragma unroll
        for (int jj = 0; jj < 2; jj++)
#pragma unroll
            for (int i = 0; i < 4; i++)
#pragma unroll
                for (int j = 0; j < 4; j++) acc[ii][jj][i][j] = 0.0f;

    for (int k0 = 0; k0 < 128; k0 += 16) {
        __syncthreads();
#pragma unroll
        for (int p = tid; p < 512; p += 256) {
            int r  = p >> 5;
            int c4 = (p & 31) << 2;
            *(float4*)&Xs[r][c4] = *(const float4*)&Xb[(k0 + r) * 256 + c4];
            *(float4*)&Ws[r][c4] = *(const float4*)&W[(k0 + r) * 128 + c4];
        }
        __syncthreads();
#pragma unroll
        for (int kk = 0; kk < 16; kk++) {
            float a[8], b[8];
            *(float4*)&a[0] = *(float4*)&Ws[kk][ty * 4];
            *(float4*)&a[4] = *(float4*)&Ws[kk][ty * 4 + 64];
            *(float4*)&b[0] = *(float4*)&Xs[kk][tx * 4];
            *(float4*)&b[4] = *(float4*)&Xs[kk][tx * 4 + 64];
#pragma unroll
            for (int ii = 0; ii < 2; ii++)
#pragma unroll
                for (int i = 0; i < 4; i++)
#pragma unroll
                    for (int jj = 0; jj < 2; jj++)
#pragma unroll
                        for (int j = 0; j < 4; j++)
                            acc[ii][jj][i][j] += a[ii * 4 + i] * b[jj * 4 + j];
        }
    }

#pragma unroll
    for (int ii = 0; ii < 2; ii++)
#pragma unroll
        for (int i = 0; i < 4; i++) {
            int nidx = ii * 64 + ty * 4 + i;
            float bvv = Bp[nidx];
#pragma unroll
            for (int jj = 0; jj < 2; jj++) {
                int col = jj * 64 + tx * 4;
                float4 o;
                o.x = acc[ii][jj][i][0] + bvv;
                o.y = acc[ii][jj][i][1] + bvv;
                o.z = acc[ii][jj][i][2] + bvv;
                o.w = acc[ii][jj][i][3] + bvv;
                if (mode == 1) {
                    o.x = gelu_tanh(o.x); o.y = gelu_tanh(o.y);
                    o.z = gelu_tanh(o.z); o.w = gelu_tanh(o.w);
                } else if (mode == 2) {
                    float4 r4 = *(const float4*)&res[bs * TOK_STRIDE + hw0 + nidx * 256 + col];
                    o.x += r4.x; o.y += r4.y; o.z += r4.z; o.w += r4.w;
                }
                *(float4*)&Ob[nidx * 256 + col] = o;
            }
        }
}

// ---------------- K3: scores + mask + softmax ----------------
// block = (b, window, head); thread (t,s) accumulates an 8192-long dot product
// (the head's 32 channels x 256 spatial are CONTIGUOUS in memory).
__global__ __launch_bounds__(256) void scores_kernel(const float* __restrict__ q,
                                                     const float* __restrict__ k,
                                                     float* __restrict__ attn) {
    __shared__ float qs[16][260];
    __shared__ float ks[16][260];
    __shared__ int toks[16];
    const int blk = blockIdx.x;          // ((b*16+n)*4+h)
    const int h = blk & 3;
    const int bn = blk >> 2;
    const int n = bn & 15;
    const int b = bn >> 4;
    const int tid = threadIdx.x;
    if (tid < 16) toks[tid] = tok_of(n, tid);
    __syncthreads();

    const int t = tid >> 4, s = tid & 15;
    float ax = 0.f, ay = 0.f, az = 0.f, aw = 0.f;

    for (int ch = 0; ch < 32; ch++) {
        __syncthreads();
#pragma unroll
        for (int j = 0; j < 8; j++) {
            int p = tid + j * 256;           // float4 index, 0..2047
            int row = p >> 6;                // 0..31  (64 float4 per row)
            int c4 = (p & 63) << 2;
            const float* src = (row < 16) ? q : k;
            int tok = toks[row & 15];
            const float* g = src + (b * 256 + tok) * TOK_STRIDE + h * 8192 + ch * 256 + c4;
            *(float4*)&((row < 16 ? qs : ks)[row & 15][c4]) = *(const float4*)g;
        }
        __syncthreads();
#pragma unroll
        for (int i4 = 0; i4 < 64; i4++) {
            float4 qv = *(float4*)&qs[t][i4 * 4];
            float4 kv = *(float4*)&ks[s][i4 * 4];
            ax += qv.x * kv.x; ay += qv.y * kv.y;
            az += qv.z * kv.z; aw += qv.w * kv.w;
        }
    }
    float acc = (ax + ay) + (az + aw);
    acc *= 6.9053396600248786e-4f;   // 1/(sqrt(32)*256)

    // Swin shifted-window mask, computed in the rolled frame
    {
        int nr = n >> 2, nc = n & 3;
        int idt = region_of(nr * 4 + (t >> 2)) * 3 + region_of(nc * 4 + (t & 3));
        int ids = region_of(nr * 4 + (s >> 2)) * 3 + region_of(nc * 4 + (s & 3));
        if (idt != ids) acc -= 1e9f;
    }

    // softmax over s within 16-lane groups
    float m = acc;
#pragma unroll
    for (int off = 8; off; off >>= 1)
        m = fmaxf(m, __shfl_xor_sync(0xffffffffu, m, off, 16));
    float e = expf(acc - m);
    float sum = e;
#pragma unroll
    for (int off = 8; off; off >>= 1)
        sum += __shfl_xor_sync(0xffffffffu, sum, off, 16);

    attn[blk * 256 + tid] = e / sum;
}

// ---------------- K4: o = attn @ V, written back at ORIGINAL token positions ----------------
// thread owns one float4 of the [128c x 256hw] feature; holds all 16 s-rows in
// registers -> each V element read from DRAM exactly once.
__global__ __launch_bounds__(256, 2) void apply_attn_kernel(const float* __restrict__ attn,
                                                            const float* __restrict__ val,
                                                            float* __restrict__ out) {
    __shared__ float at_s[16][16];
    __shared__ int toks[16];
    const int bn = blockIdx.y;
    const int b = bn >> 4, n = bn & 15;
    const int tid = threadIdx.x;
    if (tid < 16) toks[tid] = tok_of(n, tid);

    const int f0 = blockIdx.x * 1024 + tid * 4;   // flat (c,hw) float index
    const int c = f0 >> 8;
    const int hw = f0 & 255;
    const int head = c >> 5;                       // uniform within block
    at_s[tid >> 4][tid & 15] = attn[(bn * 4 + head) * 256 + tid];
    __syncthreads();

    float4 v4[16];
#pragma unroll
    for (int s = 0; s < 16; s++)
        v4[s] = *(const float4*)&val[(b * 256 + toks[s]) * CC * 256 + c * 256 + hw];

#pragma unroll
    for (int t = 0; t < 16; t++) {
        float4 o = make_float4(0.f, 0.f, 0.f, 0.f);
#pragma unroll
        for (int s = 0; s < 16; s++) {
            float a = at_s[t][s];
            o.x += a * v4[s].x; o.y += a * v4[s].y;
            o.z += a * v4[s].z; o.w += a * v4[s].w;
        }
        *(float4*)&out[(b * 256 + toks[t]) * CC * 256 + c * 256 + hw] = o;
    }
}

// ---------------- launch ----------------
extern "C" void kernel_launch(void* const* d_in, const int* in_sizes, int n_in,
                              void* d_out, int out_size) {
    const float* v  = (const float*)d_in[0];
    const float* wq = (const float*)d_in[1];
    const float* bq = (const float*)d_in[2];
    const float* wk = (const float*)d_in[3];
    const float* bk = (const float*)d_in[4];
    const float* wv = (const float*)d_in[5];
    const float* bv = (const float*)d_in[6];
    const float* wo = (const float*)d_in[7];
    const float* bo = (const float*)d_in[8];
    const float* w1 = (const float*)d_in[9];
    const float* b1 = (const float*)d_in[10];
    const float* w2 = (const float*)d_in[11];
    const float* b2 = (const float*)d_in[12];
    float* out = (float*)d_out;

    float *vn, *q, *k, *vvp, *attn;
    cudaGetSymbolAddress((void**)&vn,   g_vn);
    cudaGetSymbolAddress((void**)&q,    g_q);
    cudaGetSymbolAddress((void**)&k,    g_k);
    cudaGetSymbolAddress((void**)&vvp,  g_v);
    cudaGetSymbolAddress((void**)&attn, g_attn);

    // 1. vn = InstanceNorm(v)
    inorm_kernel<<<32768, 256>>>(v, vn);
    // 2. Q,K,V projections (fused launch: bs-major grid -> X reused via L2)
    pw_kernel<<<dim3(6, 2048), 256>>>(vn, wq, wk, wv, bq, bk, bv, q, k, vvp, nullptr, 0);
    // 3. scores + mask + softmax per (b, window, head)
    scores_kernel<<<512, 256>>>(q, k, attn);
    // 4. o = attn @ V (written at original token positions; overwrites Q buffer)
    apply_attn_kernel<<<dim3(32, 128), 256>>>(attn, vvp, q);
    // 5. d_out = v + pw(o, w_o, b_o)
    pw_kernel<<<dim3(2, 2048), 256>>>(q, wo, wo, wo, bo, bo, bo, out, out, out, v, 2);
    // 6. vn = InstanceNorm(d_out)
    inorm_kernel<<<32768, 256>>>(out, vn);
    // 7. h = gelu(pw(vn, w1, b1))  (overwrites K buffer)
    pw_kernel<<<dim3(2, 2048), 256>>>(vn, w1, w1, w1, b1, b1, b1, k, k, k, nullptr, 1);
    // 8. d_out += pw(h, w2, b2)
    pw_kernel<<<dim3(2, 2048), 256>>>(k, w2, w2, w2, b2, b2, b2, out, out, out, out, 2);
}

// round 15
// speedup vs baseline: 1.7505x; 1.7505x over previous
#include <cuda_runtime.h>
#include <math.h>

// ---------------- static config ----------------
#define BB    8
#define SS    256
#define CC    128
#define HWD   256
#define TOK_STRIDE 32768            // CC*HWD
#define TOTAL (BB*SS*CC*HWD)        // 67,108,864 floats

// ---------------- scratch ----------------
__device__ float g_q[TOTAL];        // Q, later attention output
__device__ float g_k[TOTAL];        // K, later MLP hidden
__device__ float g_v[TOTAL];        // V
__device__ float g_attn[BB*16*4*256];
__device__ float g_mean[BB*SS*CC];
__device__ float g_rsig[BB*SS*CC];

// ---------------- helpers ----------------
__device__ __forceinline__ float gelu_tanh(float x) {
    float x3 = x * x * x;
    return 0.5f * x * (1.0f + tanhf(0.7978845608028654f * (x + 0.044715f * x3)));
}
__device__ __forceinline__ float f2tf32(float x) {
    unsigned u; asm("cvt.rna.tf32.f32 %0, %1;" : "=r"(u) : "f"(x));
    return __uint_as_float(u);
}
__device__ __forceinline__ int tok_of(int n, int slot) {
    int nr = n >> 2, nc = n & 3;
    int pr = nr * 4 + (slot >> 2), pc = nc * 4 + (slot & 3);
    return (((pr + 2) & 15) << 4) | ((pc + 2) & 15);
}
__device__ __forceinline__ int region_of(int p) { return p < 12 ? 0 : (p < 14 ? 1 : 2); }

// ---------------- stats: per-(b,s,c) mean & rsqrt(var+eps) over 256 spatial ----------------
__global__ __launch_bounds__(256) void stats_kernel(const float* __restrict__ in,
                                                    float* __restrict__ mean,
                                                    float* __restrict__ rsig) {
    int row  = blockIdx.x * 8 + (threadIdx.x >> 5);
    int lane = threadIdx.x & 31;
    const float* p = in + row * 256 + lane * 8;
    float4 a = *(const float4*)p;
    float4 b = *(const float4*)(p + 4);
    float s = a.x + a.y + a.z + a.w + b.x + b.y + b.z + b.w;
    float q = a.x*a.x + a.y*a.y + a.z*a.z + a.w*a.w
            + b.x*b.x + b.y*b.y + b.z*b.z + b.w*b.w;
#pragma unroll
    for (int off = 16; off; off >>= 1) {
        s += __shfl_xor_sync(0xffffffffu, s, off);
        q += __shfl_xor_sync(0xffffffffu, q, off);
    }
    if (lane == 0) {
        float m = s * (1.0f / 256.0f);
        float var = q * (1.0f / 256.0f) - m * m;
        mean[row] = m;
        rsig[row] = rsqrtf(var + 1e-5f);
    }
}

// ---------------- tf32 tensor-core pointwise GEMM ----------------
// Per bs token: Out[d=128][hw=256] = sum_c Xn[c][hw] * W[c][d] + bias
// Block = (mat, bs). 256 thr = 8 warps (2x4), warp tile 64x64, mma m16n8k8.
// Optional on-the-fly InstanceNorm of X (mean/rsig per (bs,c)).
// mode: 0 = store, 1 = gelu, 2 = +residual
__global__ __launch_bounds__(256, 1) void pw_mma_kernel(
    const float* __restrict__ X,
    const float* __restrict__ W0, const float* __restrict__ W1, const float* __restrict__ W2,
    const float* __restrict__ B0, const float* __restrict__ B1, const float* __restrict__ B2,
    float* __restrict__ O0, float* __restrict__ O1, float* __restrict__ O2,
    const float* __restrict__ mean, const float* __restrict__ rsig,
    const float* __restrict__ res, int mode)
{
    __shared__ float Xs[16][264];   // [k][hw]  stride%32 == 8 -> conflict-free frags
    __shared__ float Ws[16][136];   // [k][d]

    const int bs  = blockIdx.y;
    const int mat = blockIdx.x;
    const float* W  = (mat == 0) ? W0 : (mat == 1 ? W1 : W2);
    const float* Bp = (mat == 0) ? B0 : (mat == 1 ? B1 : B2);
    float*       O  = (mat == 0) ? O0 : (mat == 1 ? O1 : O2);
    const float* Xb = X + (size_t)bs * TOK_STRIDE;
    float*       Ob = O + (size_t)bs * TOK_STRIDE;

    const int tid  = threadIdx.x;
    const int warp = tid >> 5, lane = tid & 31;
    const int gid  = lane >> 2, tig = lane & 3;
    const int m_warp = (warp >> 2) * 64;
    const int n_warp = (warp & 3) * 64;

    // gmem tile-load mapping
    const int xr = tid >> 6;            // X rows: xr + j*4   (j=0..3), 64 f4/row
    const int xc = (tid & 63) << 2;
    const int wr = tid >> 5;            // W rows: wr + j*8   (j=0..1), 32 f4/row
    const int wc = (tid & 31) << 2;

    float acc[4][8][4];
#pragma unroll
    for (int a = 0; a < 4; a++)
#pragma unroll
        for (int b = 0; b < 8; b++)
#pragma unroll
            for (int c = 0; c < 4; c++) acc[a][b][c] = 0.0f;

    float4 xf[4]; float4 wf[2]; float mk[4], rk[4];

#define LOAD_TILE(K0) do {                                                        \
    _Pragma("unroll")                                                             \
    for (int j = 0; j < 4; j++)                                                   \
        xf[j] = *(const float4*)&Xb[(size_t)((K0) + xr + j*4) * 256 + xc];        \
    if (mean) {                                                                   \
        _Pragma("unroll")                                                         \
        for (int j = 0; j < 4; j++) {                                             \
            int cc_ = (K0) + xr + j*4;                                            \
            mk[j] = __ldg(&mean[bs * 128 + cc_]);                                 \
            rk[j] = __ldg(&rsig[bs * 128 + cc_]);                                 \
        }                                                                         \
    }                                                                             \
    _Pragma("unroll")                                                             \
    for (int j = 0; j < 2; j++)                                                   \
        wf[j] = *(const float4*)&W[((K0) + wr + j*8) * 128 + wc];                 \
} while (0)

#define STORE_TILE() do {                                                         \
    _Pragma("unroll")                                                             \
    for (int j = 0; j < 4; j++) {                                                 \
        float4 t = xf[j];                                                         \
        if (mean) {                                                               \
            t.x = (t.x - mk[j]) * rk[j]; t.y = (t.y - mk[j]) * rk[j];             \
            t.z = (t.z - mk[j]) * rk[j]; t.w = (t.w - mk[j]) * rk[j];             \
        }                                                                         \
        int r = xr + j*4;                                                         \
        Xs[r][xc+0] = f2tf32(t.x); Xs[r][xc+1] = f2tf32(t.y);                     \
        Xs[r][xc+2] = f2tf32(t.z); Xs[r][xc+3] = f2tf32(t.w);                     \
    }                                                                             \
    _Pragma("unroll")                                                             \
    for (int j = 0; j < 2; j++) {                                                 \
        int r = wr + j*8;                                                         \
        Ws[r][wc+0] = f2tf32(wf[j].x); Ws[r][wc+1] = f2tf32(wf[j].y);             \
        Ws[r][wc+2] = f2tf32(wf[j].z); Ws[r][wc+3] = f2tf32(wf[j].w);             \
    }                                                                             \
} while (0)

    LOAD_TILE(0);
#pragma unroll 1
    for (int t = 0; t < 8; t++) {
        __syncthreads();
        STORE_TILE();
        __syncthreads();
        if (t < 7) LOAD_TILE((t + 1) * 16);

#pragma unroll
        for (int k8 = 0; k8 < 2; k8++) {
            const int kb = k8 * 8;
            unsigned af[4][4];
#pragma unroll
            for (int mt = 0; mt < 4; mt++) {
                int mb = m_warp + mt * 16;
                af[mt][0] = __float_as_uint(Ws[kb + tig    ][mb + gid    ]);
                af[mt][1] = __float_as_uint(Ws[kb + tig    ][mb + gid + 8]);
                af[mt][2] = __float_as_uint(Ws[kb + tig + 4][mb + gid    ]);
                af[mt][3] = __float_as_uint(Ws[kb + tig + 4][mb + gid + 8]);
            }
#pragma unroll
            for (int nt = 0; nt < 8; nt++) {
                int nb = n_warp + nt * 8 + gid;
                unsigned b0 = __float_as_uint(Xs[kb + tig    ][nb]);
                unsigned b1 = __float_as_uint(Xs[kb + tig + 4][nb]);
#pragma unroll
                for (int mt = 0; mt < 4; mt++) {
                    float* c = acc[mt][nt];
                    asm volatile(
                        "mma.sync.aligned.m16n8k8.row.col.f32.tf32.tf32.f32 "
                        "{%0,%1,%2,%3}, {%4,%5,%6,%7}, {%8,%9}, {%0,%1,%2,%3};"
                        : "+f"(c[0]), "+f"(c[1]), "+f"(c[2]), "+f"(c[3])
                        : "r"(af[mt][0]), "r"(af[mt][1]), "r"(af[mt][2]), "r"(af[mt][3]),
                          "r"(b0), "r"(b1));
                }
            }
        }
    }
#undef LOAD_TILE
#undef STORE_TILE

    // epilogue: bias (+gelu | +residual), float2 stores
    const float* Rb = res ? res + (size_t)bs * TOK_STRIDE : nullptr;
#pragma unroll
    for (int mt = 0; mt < 4; mt++) {
        int m0 = m_warp + mt * 16 + gid;
        float bv0 = __ldg(&Bp[m0]);
        float bv1 = __ldg(&Bp[m0 + 8]);
#pragma unroll
        for (int nt = 0; nt < 8; nt++) {
            int col = n_warp + nt * 8 + 2 * tig;
            float2 o0 = make_float2(acc[mt][nt][0] + bv0, acc[mt][nt][1] + bv0);
            float2 o1 = make_float2(acc[mt][nt][2] + bv1, acc[mt][nt][3] + bv1);
            if (mode == 1) {
                o0.x = gelu_tanh(o0.x); o0.y = gelu_tanh(o0.y);
                o1.x = gelu_tanh(o1.x); o1.y = gelu_tanh(o1.y);
            } else if (mode == 2) {
                float2 r0 = *(const float2*)&Rb[m0 * 256 + col];
                float2 r1 = *(const float2*)&Rb[(m0 + 8) * 256 + col];
                o0.x += r0.x; o0.y += r0.y;
                o1.x += r1.x; o1.y += r1.y;
            }
            *(float2*)&Ob[m0 * 256 + col]       = o0;
            *(float2*)&Ob[(m0 + 8) * 256 + col] = o1;
        }
    }
}

// ---------------- scores + mask + softmax (unchanged, passing) ----------------
__global__ __launch_bounds__(256) void scores_kernel(const float* __restrict__ q,
                                                     const float* __restrict__ k,
                                                     float* __restrict__ attn) {
    __shared__ float qs[16][260];
    __shared__ float ks[16][260];
    __shared__ int toks[16];
    const int blk = blockIdx.x;
    const int h = blk & 3;
    const int bn = blk >> 2;
    const int n = bn & 15;
    const int b = bn >> 4;
    const int tid = threadIdx.x;
    if (tid < 16) toks[tid] = tok_of(n, tid);
    __syncthreads();

    const int t = tid >> 4, s = tid & 15;
    float ax = 0.f, ay = 0.f, az = 0.f, aw = 0.f;

    for (int ch = 0; ch < 32; ch++) {
        __syncthreads();
#pragma unroll
        for (int j = 0; j < 8; j++) {
            int p = tid + j * 256;
            int row = p >> 6;
            int c4 = (p & 63) << 2;
            const float* src = (row < 16) ? q : k;
            int tok = toks[row & 15];
            const float* g = src + ((size_t)(b * 256 + tok)) * TOK_STRIDE + h * 8192 + ch * 256 + c4;
            *(float4*)&((row < 16 ? qs : ks)[row & 15][c4]) = *(const float4*)g;
        }
        __syncthreads();
#pragma unroll
        for (int i4 = 0; i4 < 64; i4++) {
            float4 qv = *(float4*)&qs[t][i4 * 4];
            float4 kv = *(float4*)&ks[s][i4 * 4];
            ax += qv.x * kv.x; ay += qv.y * kv.y;
            az += qv.z * kv.z; aw += qv.w * kv.w;
        }
    }
    float acc = (ax + ay) + (az + aw);
    acc *= 6.9053396600248786e-4f;

    {
        int nr = n >> 2, nc = n & 3;
        int idt = region_of(nr * 4 + (t >> 2)) * 3 + region_of(nc * 4 + (t & 3));
        int ids = region_of(nr * 4 + (s >> 2)) * 3 + region_of(nc * 4 + (s & 3));
        if (idt != ids) acc -= 1e9f;
    }

    float m = acc;
#pragma unroll
    for (int off = 8; off; off >>= 1)
        m = fmaxf(m, __shfl_xor_sync(0xffffffffu, m, off, 16));
    float e = expf(acc - m);
    float sum = e;
#pragma unroll
    for (int off = 8; off; off >>= 1)
        sum += __shfl_xor_sync(0xffffffffu, sum, off, 16);

    attn[blk * 256 + tid] = e / sum;
}

// ---------------- attn @ V (unchanged, passing; 72% DRAM SOL) ----------------
__global__ __launch_bounds__(256, 2) void apply_attn_kernel(const float* __restrict__ attn,
                                                            const float* __restrict__ val,
                                                            float* __restrict__ out) {
    __shared__ float at_s[16][16];
    __shared__ int toks[16];
    const int bn = blockIdx.y;
    const int b = bn >> 4, n = bn & 15;
    const int tid = threadIdx.x;
    if (tid < 16) toks[tid] = tok_of(n, tid);

    const int f0 = blockIdx.x * 1024 + tid * 4;
    const int c = f0 >> 8;
    const int hw = f0 & 255;
    const int head = c >> 5;
    at_s[tid >> 4][tid & 15] = attn[(bn * 4 + head) * 256 + tid];
    __syncthreads();

    float4 v4[16];
#pragma unroll
    for (int s = 0; s < 16; s++)
        v4[s] = *(const float4*)&val[((size_t)(b * 256 + toks[s])) * TOK_STRIDE + c * 256 + hw];

#pragma unroll
    for (int t = 0; t < 16; t++) {
        float4 o = make_float4(0.f, 0.f, 0.f, 0.f);
#pragma unroll
        for (int s = 0; s < 16; s++) {
            float a = at_s[t][s];
            o.x += a * v4[s].x; o.y += a * v4[s].y;
            o.z += a * v4[s].z; o.w += a * v4[s].w;
        }
        *(float4*)&out[((size_t)(b * 256 + toks[t])) * TOK_STRIDE + c * 256 + hw] = o;
    }
}

// ---------------- launch ----------------
extern "C" void kernel_launch(void* const* d_in, const int* in_sizes, int n_in,
                              void* d_out, int out_size) {
    const float* v  = (const float*)d_in[0];
    const float* wq = (const float*)d_in[1];
    const float* bq = (const float*)d_in[2];
    const float* wk = (const float*)d_in[3];
    const float* bk = (const float*)d_in[4];
    const float* wv = (const float*)d_in[5];
    const float* bv = (const float*)d_in[6];
    const float* wo = (const float*)d_in[7];
    const float* bo = (const float*)d_in[8];
    const float* w1 = (const float*)d_in[9];
    const float* b1 = (const float*)d_in[10];
    const float* w2 = (const float*)d_in[11];
    const float* b2 = (const float*)d_in[12];
    float* out = (float*)d_out;

    float *q, *k, *vvp, *attn, *mean, *rsig;
    cudaGetSymbolAddress((void**)&q,    g_q);
    cudaGetSymbolAddress((void**)&k,    g_k);
    cudaGetSymbolAddress((void**)&vvp,  g_v);
    cudaGetSymbolAddress((void**)&attn, g_attn);
    cudaGetSymbolAddress((void**)&mean, g_mean);
    cudaGetSymbolAddress((void**)&rsig, g_rsig);

    // 1. InstanceNorm stats of v
    stats_kernel<<<32768, 256>>>(v, mean, rsig);
    // 2. Q,K,V projections with fused normalization (tf32 tensor cores)
    pw_mma_kernel<<<dim3(3, 2048), 256>>>(v, wq, wk, wv, bq, bk, bv,
                                          q, k, vvp, mean, rsig, nullptr, 0);
    // 3. scores + mask + softmax
    scores_kernel<<<512, 256>>>(q, k, attn);
    // 4. o = attn @ V (overwrites Q buffer)
    apply_attn_kernel<<<dim3(32, 128), 256>>>(attn, vvp, q);
    // 5. mid = v + pw(o, w_o)
    pw_mma_kernel<<<dim3(1, 2048), 256>>>(q, wo, wo, wo, bo, bo, bo,
                                          out, out, out, nullptr, nullptr, v, 2);
    // 6. InstanceNorm stats of mid
    stats_kernel<<<32768, 256>>>(out, mean, rsig);
    // 7. h = gelu(pw(norm(mid), w1))   (overwrites K buffer)
    pw_mma_kernel<<<dim3(1, 2048), 256>>>(out, w1, w1, w1, b1, b1, b1,
                                          k, k, k, mean, rsig, nullptr, 1);
    // 8. out = mid + pw(h, w2)
    pw_mma_kernel<<<dim3(1, 2048), 256>>>(k, w2, w2, w2, b2, b2, b2,
                                          out, out, out, nullptr, nullptr, out, 2);
}